// round 9
// baseline (speedup 1.0000x reference)
#include <cuda_runtime.h>

#define NN 20000
#define NE 320000
#define NG 256
#define NA 23
#define NB 7
#define M0 64
#define M1 24
#define M2 16
#define MDIM 64

__device__ __align__(16) float g_wv[3381];                 // WV[(jv*7+v)*23 + u]
__device__ __align__(16) float g_yv[(size_t)NN * 168];     // yv[n][jv(21)*8 + v(7)]
__device__ __align__(16) float g_ead[(size_t)NE * 8];      // dst-sorted ea, padded
__device__ __align__(16) float g_shd[(size_t)NE * 8];      // dst-sorted sh1(3),sh2(5)
__device__ __align__(16) float g_m[(size_t)NN * MDIM];
__device__ float g_ge[NE];                                 // per-edge g, dst-sorted
__device__ int g_cnt_d[NN], g_cur_d[NN], g_start_d[NN];
__device__ int g_cnt_s[NN], g_cur_s[NN], g_start_s[NN];
__device__ int g_desrc[NE];
__device__ int g_spos[NE];

#define A1  0.078811041f
#define C0  0.047245559f
#define C1  0.044543540f
#define C2  0.042257713f
#define S3  1.7320508075688772f
#define S5  2.23606797749979f
#define S15 3.872983346207417f

__global__ void k_zero(float* __restrict__ out) {
    int i = blockIdx.x * blockDim.x + threadIdx.x;
    int stride = gridDim.x * blockDim.x;
    for (int j = i; j < NN; j += stride) { g_cnt_d[j] = 0; g_cnt_s[j] = 0; }
    for (int j = i; j < NG; j += stride) out[j] = 0.f;
}

__global__ void k_count(const int* __restrict__ ei) {
    int e = blockIdx.x * blockDim.x + threadIdx.x;
    if (e < NE) {
        atomicAdd(&g_cnt_s[ei[e]], 1);
        atomicAdd(&g_cnt_d[ei[NE + e]], 1);
    }
}

__global__ void __launch_bounds__(1024) k_scan() {
    __shared__ int sums[1024];
    int t = threadIdx.x;
    int base = t * 20;
    {
        int local[20]; int s = 0;
#pragma unroll
        for (int i = 0; i < 20; i++) {
            int idx = base + i;
            int c = (idx < NN) ? g_cnt_d[idx] : 0;
            local[i] = s; s += c;
        }
        sums[t] = s;
        __syncthreads();
        for (int d = 1; d < 1024; d <<= 1) {
            int v = (t >= d) ? sums[t - d] : 0;
            __syncthreads();
            if (t >= d) sums[t] += v;
            __syncthreads();
        }
        int excl = (t == 0) ? 0 : sums[t - 1];
#pragma unroll
        for (int i = 0; i < 20; i++) {
            int idx = base + i;
            if (idx < NN) { g_cur_d[idx] = excl + local[i]; g_start_d[idx] = excl + local[i]; }
        }
        __syncthreads();
    }
    {
        int local[20]; int s = 0;
#pragma unroll
        for (int i = 0; i < 20; i++) {
            int idx = base + i;
            int c = (idx < NN) ? g_cnt_s[idx] : 0;
            local[i] = s; s += c;
        }
        sums[t] = s;
        __syncthreads();
        for (int d = 1; d < 1024; d <<= 1) {
            int v = (t >= d) ? sums[t - d] : 0;
            __syncthreads();
            if (t >= d) sums[t] += v;
            __syncthreads();
        }
        int excl = (t == 0) ? 0 : sums[t - 1];
#pragma unroll
        for (int i = 0; i < 20; i++) {
            int idx = base + i;
            if (idx < NN) { g_cur_s[idx] = excl + local[i]; g_start_s[idx] = excl + local[i]; }
        }
    }
}

// fill: dst-sorted staging (ea, sh, src); src-order: dst position
__global__ void k_fill(const int* __restrict__ ei, const float* __restrict__ ea,
                       const float* __restrict__ pos) {
    int e = blockIdx.x * blockDim.x + threadIdx.x;
    if (e >= NE) return;
    int src = ei[e];
    int dst = ei[NE + e];
    int pd = atomicAdd(&g_cur_d[dst], 1);
    g_desrc[pd] = src;

    float a0 = __ldg(ea + e*7 + 0), a1 = __ldg(ea + e*7 + 1);
    float a2 = __ldg(ea + e*7 + 2), a3 = __ldg(ea + e*7 + 3);
    float a4 = __ldg(ea + e*7 + 4), a5 = __ldg(ea + e*7 + 5);
    float a6 = __ldg(ea + e*7 + 6);
    float4* eap = (float4*)(g_ead + (size_t)pd * 8);
    eap[0] = make_float4(a0, a1, a2, a3);
    eap[1] = make_float4(a4, a5, a6, 0.f);

    float px = __ldg(pos + src*3+0) - __ldg(pos + dst*3+0);
    float py = __ldg(pos + src*3+1) - __ldg(pos + dst*3+1);
    float pz = __ldg(pos + src*3+2) - __ldg(pos + dst*3+2);
    float r2 = px*px + py*py + pz*pz;
    float4* shp = (float4*)(g_shd + (size_t)pd * 8);
    shp[0] = make_float4(S3*px, S3*py, S3*pz, S15*px*py);
    shp[1] = make_float4(S15*py*pz, 0.5f*S5*(3.f*pz*pz - r2),
                         S15*px*pz, 0.5f*S15*(px*px - py*py));

    int ps = atomicAdd(&g_cur_s[src], 1);
    g_spos[ps] = pd;
}

// WV[(jv*7+v)*23+u] = scale_j * sum_w W_j[u,v,w] * V_j[w, v']
__global__ void k_wv(const float* __restrict__ W1, const float* __restrict__ W2,
                     const float* __restrict__ W3, const float* __restrict__ V1,
                     const float* __restrict__ V2, const float* __restrict__ V3) {
    int o = blockIdx.x * 512 + threadIdx.x;
    if (o >= 3381) return;
    int u = o % 23;
    int t = o / 23;
    int v = t % 7;
    int jv = t / 7;
    int j = jv / 7, vp = jv % 7;
    float r = 0.f;
    if (j == 0) {
        for (int w = 0; w < M0; w++) r = fmaf(W1[(u*7+v)*M0 + w], V1[w*7 + vp], r);
        r *= A1 * C0;
    } else if (j == 1) {
        for (int w = 0; w < M1; w++) r = fmaf(W2[(u*7+v)*M1 + w], V2[w*7 + vp], r);
        r *= A1 * C1;
    } else {
        for (int w = 0; w < M2; w++) r = fmaf(W3[(u*7+v)*M2 + w], V3[w*7 + vp], r);
        r *= A1 * C2;
    }
    g_wv[o] = r;
}

// yv[n, jv*8 + v] = sum_u x[n,u] * WV[(jv*7+v)*23 + u]
__global__ void __launch_bounds__(160) k_yv(const float* __restrict__ x) {
    __shared__ float xs[NA];
    int t = threadIdx.x;
    bool act = t < 147;
    float wreg[NA];
    if (act) {
#pragma unroll
        for (int u = 0; u < NA; u++) wreg[u] = g_wv[t * 23 + u];
    }
    int jv = t / 7, v = t % 7;
    int off = jv * 8 + v;
    for (int n = blockIdx.x; n < NN; n += gridDim.x) {
        __syncthreads();
        if (t < NA) xs[t] = x[n * NA + t];
        __syncthreads();
        if (!act) continue;
        float r = 0.f;
#pragma unroll
        for (int u = 0; u < NA; u++) r = fmaf(xs[u], wreg[u], r);
        g_yv[(size_t)n * 168 + off] = r;
    }
}

// maccum: warp per dst node. Lanes 0-20 compute z[jv] cooperatively
// (coalesced yv row load), shuffle distributes to output lanes.
__global__ void __launch_bounds__(256) k_maccum() {
    int warp = (blockIdx.x * 256 + threadIdx.x) >> 5;
    int lane = threadIdx.x & 31;
    if (warp >= NN) return;
    int n = warp;
    int start = g_start_d[n];
    int cnt = g_cnt_d[n];

    int o0 = lane, o1 = lane + 32;
    int jv0, si0, jv1 = 0, si1 = 8;
    if (o0 < 7)       { jv0 = o0; si0 = 8; }
    else if (o0 < 28) { int q = o0 - 7;  jv0 = 7 + q / 3;  si0 = q % 3; }
    else              { int q = o0 - 28; jv0 = 14 + q / 5; si0 = 3 + q % 5; }
    bool v1ok = o1 < 63;
    if (v1ok) {
        if (o1 < 28) { int q = o1 - 7;  jv1 = 7 + q / 3;  si1 = q % 3; }
        else         { int q = o1 - 28; jv1 = 14 + q / 5; si1 = 3 + q % 5; }
    }

    float acc0 = 0.f, acc1 = 0.f;

#define MBODY(ii) { \
    int base = start + (ii); \
    int s = g_desrc[base]; \
    const float4* eap = (const float4*)(g_ead + (size_t)base * 8); \
    float4 e0 = __ldg(eap), e1 = __ldg(eap + 1); \
    float z = 0.f; \
    if (lane < 21) { \
        const float4* yp = (const float4*)(g_yv + (size_t)s * 168 + lane * 8); \
        float4 p = __ldg(yp), q = __ldg(yp + 1); \
        z = e0.x*p.x + e0.y*p.y + e0.z*p.z + e0.w*p.w \
          + e1.x*q.x + e1.y*q.y + e1.z*q.z; \
    } \
    float z0 = __shfl_sync(0xffffffffu, z, jv0); \
    float z1 = __shfl_sync(0xffffffffu, z, jv1); \
    const float* shp = g_shd + (size_t)base * 8; \
    float h0 = (si0 < 8) ? __ldg(shp + si0) : 1.f; \
    float h1 = (si1 < 8) ? __ldg(shp + si1) : 1.f; \
    acc0 = fmaf(z0, h0, acc0); \
    if (v1ok) acc1 = fmaf(z1, h1, acc1); \
}

    int i = 0;
    for (; i + 2 <= cnt; i += 2) { MBODY(i); MBODY(i + 1); }
    if (i < cnt) { MBODY(i); }
#undef MBODY

    g_m[(size_t)n * MDIM + o0] = acc0;
    if (v1ok) g_m[(size_t)n * MDIM + o1] = acc1;
    else if (lane == 31) g_m[(size_t)n * MDIM + 63] = 0.f;
}

__device__ __forceinline__ float sel8(float4 a, float4 b, int i) {
    float lo = (i == 0) ? a.x : (i == 1) ? a.y : (i == 2) ? a.z : a.w;
    float hi = (i == 4) ? b.x : (i == 5) ? b.y : (i == 6) ? b.z : b.w;
    return (i < 4) ? lo : hi;
}

// pass2: warp per SRC node, m row resident in lane registers.
// g(e) = sum_o m[s,o] * ea[e,v(o)] * sh(e,si(o)); stored at dst position.
__global__ void __launch_bounds__(256) k_pass2s() {
    int warp = (blockIdx.x * 256 + threadIdx.x) >> 5;
    int lane = threadIdx.x & 31;
    if (warp >= NN) return;
    int s = warp;

    int o0 = lane, o1 = lane + 32;
    int v0, si0, v1 = 0, si1 = 8;
    if (o0 < 7)       { v0 = o0; si0 = 8; }
    else if (o0 < 28) { int q = o0 - 7;  v0 = q / 3; si0 = q % 3; }
    else              { int q = o0 - 28; v0 = q / 5; si0 = 3 + q % 5; }
    bool v1ok = o1 < 63;
    if (v1ok) {
        if (o1 < 28) { int q = o1 - 7;  v1 = q / 3; si1 = q % 3; }
        else         { int q = o1 - 28; v1 = q / 5; si1 = 3 + q % 5; }
    }

    float m0 = __ldg(g_m + (size_t)s * MDIM + o0);           // coalesced
    float m1 = __ldg(g_m + (size_t)s * MDIM + o1);           // m[63] = 0

    int start = g_start_s[s];
    int cnt = g_cnt_s[s];

    for (int i = 0; i < cnt; i++) {
        int pd = g_spos[start + i];
        const float4* eap = (const float4*)(g_ead + (size_t)pd * 8);
        float4 e0 = __ldg(eap), e1 = __ldg(eap + 1);
        const float4* shp = (const float4*)(g_shd + (size_t)pd * 8);
        float4 h0 = __ldg(shp), h1 = __ldg(shp + 1);

        float a0 = sel8(e0, e1, v0);
        float hh0 = (si0 < 8) ? sel8(h0, h1, si0) : 1.f;
        float p = m0 * a0 * hh0;
        float a1v = sel8(e0, e1, v1);
        float hh1 = (si1 < 8) ? sel8(h0, h1, si1) : 1.f;
        p += v1ok ? (m1 * a1v * hh1) : 0.f;

#pragma unroll
        for (int off = 16; off > 0; off >>= 1)
            p += __shfl_xor_sync(0xffffffffu, p, off);
        if (lane == 0) g_ge[pd] = p;
    }
}

// final: warp per dst node, sum per-edge g, one atomic per node
__global__ void __launch_bounds__(256) k_final(
    const int* __restrict__ batch, float* __restrict__ out)
{
    int warp = (blockIdx.x * 256 + threadIdx.x) >> 5;
    int lane = threadIdx.x & 31;
    if (warp >= NN) return;
    int n = warp;
    int start = g_start_d[n];
    int cnt = g_cnt_d[n];

    float gsum = 0.f;
    for (int i = lane; i < cnt; i += 32) gsum += g_ge[start + i];
#pragma unroll
    for (int off = 16; off > 0; off >>= 1)
        gsum += __shfl_xor_sync(0xffffffffu, gsum, off);
    if (lane == 0) atomicAdd(&out[batch[n]], gsum);
}

extern "C" void kernel_launch(void* const* d_in, const int* in_sizes, int n_in,
                              void* d_out, int out_size) {
    const float* pos   = (const float*)d_in[0];
    const float* x     = (const float*)d_in[1];
    const float* ea    = (const float*)d_in[2];
    const int*   ei    = (const int*)d_in[3];
    const int*   batch = (const int*)d_in[4];
    const float* W1    = (const float*)d_in[5];
    const float* W2    = (const float*)d_in[6];
    const float* W3    = (const float*)d_in[7];
    const float* V1    = (const float*)d_in[8];
    const float* V2    = (const float*)d_in[9];
    const float* V3    = (const float*)d_in[10];
    float* out = (float*)d_out;

    k_zero<<<80, 256>>>(out);
    k_count<<<(NE + 255) / 256, 256>>>(ei);
    k_scan<<<1, 1024>>>();
    k_fill<<<(NE + 255) / 256, 256>>>(ei, ea, pos);
    k_wv<<<7, 512>>>(W1, W2, W3, V1, V2, V3);
    k_yv<<<1480, 160>>>(x);
    k_maccum<<<(NN * 32 + 255) / 256, 256>>>();
    k_pass2s<<<(NN * 32 + 255) / 256, 256>>>();
    k_final<<<(NN * 32 + 255) / 256, 256>>>(batch, out);
}

// round 10
// speedup vs baseline: 1.0751x; 1.0751x over previous
#include <cuda_runtime.h>

#define NN 20000
#define NE 320000
#define NG 256
#define NA 23
#define NB 7
#define M0 64
#define M1 24
#define M2 16
#define MDIM 64

__device__ __align__(16) float g_wv[3381];                 // WV[(jv*7+v)*23 + u]
__device__ __align__(16) float g_yv[(size_t)NN * 168];     // yv[n][jv(21)*8 + v(7)]
__device__ __align__(16) float g_ea8[(size_t)NE * 8];      // ea at edge idx, padded
__device__ __align__(16) float g_sh8[(size_t)NE * 8];      // sh at edge idx
__device__ __align__(16) float g_m[(size_t)NN * MDIM];
__device__ int g_cnt_d[NN], g_cur_d[NN], g_start_d[NN];
__device__ int g_deid[NE], g_desrc[NE];                    // dst-sorted edge id + src

#define A1  0.078811041f
#define C0  0.047245559f
#define C1  0.044543540f
#define C2  0.042257713f
#define S3  1.7320508075688772f
#define S5  2.23606797749979f
#define S15 3.872983346207417f

__global__ void k_zero(float* __restrict__ out) {
    int i = blockIdx.x * blockDim.x + threadIdx.x;
    int stride = gridDim.x * blockDim.x;
    for (int j = i; j < NN; j += stride) g_cnt_d[j] = 0;
    for (int j = i; j < NG; j += stride) out[j] = 0.f;
}

__global__ void k_count(const int* __restrict__ ei) {
    int e = blockIdx.x * blockDim.x + threadIdx.x;
    if (e < NE) atomicAdd(&g_cnt_d[ei[NE + e]], 1);
}

__global__ void __launch_bounds__(1024) k_scan() {
    __shared__ int sums[1024];
    int t = threadIdx.x;
    int base = t * 20;
    int local[20]; int s = 0;
#pragma unroll
    for (int i = 0; i < 20; i++) {
        int idx = base + i;
        int c = (idx < NN) ? g_cnt_d[idx] : 0;
        local[i] = s; s += c;
    }
    sums[t] = s;
    __syncthreads();
    for (int d = 1; d < 1024; d <<= 1) {
        int v = (t >= d) ? sums[t - d] : 0;
        __syncthreads();
        if (t >= d) sums[t] += v;
        __syncthreads();
    }
    int excl = (t == 0) ? 0 : sums[t - 1];
#pragma unroll
    for (int i = 0; i < 20; i++) {
        int idx = base + i;
        if (idx < NN) { g_cur_d[idx] = excl + local[i]; g_start_d[idx] = excl + local[i]; }
    }
}

// fill: dst-sort index only (scattered ints); ea/sh staged COALESCED at edge idx
__global__ void k_fill(const int* __restrict__ ei, const float* __restrict__ ea,
                       const float* __restrict__ pos) {
    int e = blockIdx.x * blockDim.x + threadIdx.x;
    if (e >= NE) return;
    int src = ei[e];
    int dst = ei[NE + e];
    int pd = atomicAdd(&g_cur_d[dst], 1);
    g_deid[pd] = e;
    g_desrc[pd] = src;

    float a0 = __ldg(ea + e*7 + 0), a1 = __ldg(ea + e*7 + 1);
    float a2 = __ldg(ea + e*7 + 2), a3 = __ldg(ea + e*7 + 3);
    float a4 = __ldg(ea + e*7 + 4), a5 = __ldg(ea + e*7 + 5);
    float a6 = __ldg(ea + e*7 + 6);
    float4* eap = (float4*)(g_ea8 + (size_t)e * 8);
    eap[0] = make_float4(a0, a1, a2, a3);
    eap[1] = make_float4(a4, a5, a6, 0.f);

    float px = __ldg(pos + src*3+0) - __ldg(pos + dst*3+0);
    float py = __ldg(pos + src*3+1) - __ldg(pos + dst*3+1);
    float pz = __ldg(pos + src*3+2) - __ldg(pos + dst*3+2);
    float r2 = px*px + py*py + pz*pz;
    float4* shp = (float4*)(g_sh8 + (size_t)e * 8);
    shp[0] = make_float4(S3*px, S3*py, S3*pz, S15*px*py);
    shp[1] = make_float4(S15*py*pz, 0.5f*S5*(3.f*pz*pz - r2),
                         S15*px*pz, 0.5f*S15*(px*px - py*py));
}

// WV[(jv*7+v)*23+u] = scale_j * sum_w W_j[u,v,w] * V_j[w, v']
__global__ void k_wv(const float* __restrict__ W1, const float* __restrict__ W2,
                     const float* __restrict__ W3, const float* __restrict__ V1,
                     const float* __restrict__ V2, const float* __restrict__ V3) {
    int o = blockIdx.x * 512 + threadIdx.x;
    if (o >= 3381) return;
    int u = o % 23;
    int t = o / 23;
    int v = t % 7;
    int jv = t / 7;
    int j = jv / 7, vp = jv % 7;
    float r = 0.f;
    if (j == 0) {
        for (int w = 0; w < M0; w++) r = fmaf(W1[(u*7+v)*M0 + w], V1[w*7 + vp], r);
        r *= A1 * C0;
    } else if (j == 1) {
        for (int w = 0; w < M1; w++) r = fmaf(W2[(u*7+v)*M1 + w], V2[w*7 + vp], r);
        r *= A1 * C1;
    } else {
        for (int w = 0; w < M2; w++) r = fmaf(W3[(u*7+v)*M2 + w], V3[w*7 + vp], r);
        r *= A1 * C2;
    }
    g_wv[o] = r;
}

// yv[n, jv*8 + v] = sum_u x[n,u] * WV[(jv*7+v)*23 + u]
__global__ void __launch_bounds__(160) k_yv(const float* __restrict__ x) {
    __shared__ float xs[NA];
    int t = threadIdx.x;
    bool act = t < 147;
    float wreg[NA];
    if (act) {
#pragma unroll
        for (int u = 0; u < NA; u++) wreg[u] = g_wv[t * 23 + u];
    }
    int jv = t / 7, v = t % 7;
    int off = jv * 8 + v;
    for (int n = blockIdx.x; n < NN; n += gridDim.x) {
        __syncthreads();
        if (t < NA) xs[t] = x[n * NA + t];
        __syncthreads();
        if (!act) continue;
        float r = 0.f;
#pragma unroll
        for (int u = 0; u < NA; u++) r = fmaf(xs[u], wreg[u], r);
        g_yv[(size_t)n * 168 + off] = r;
    }
}

// maccum: warp per dst node; m[n,o] = sum_e sh(e,si(o)) * (ea[e,:].yv[src,jv(o),:])
// (identical structure to the 184us build; ea/sh via g_deid broadcast)
__global__ void __launch_bounds__(256) k_maccum() {
    int warp = (blockIdx.x * 256 + threadIdx.x) >> 5;
    int lane = threadIdx.x & 31;
    if (warp >= NN) return;
    int n = warp;
    int start = g_start_d[n];
    int cnt = g_cnt_d[n];

    int o0 = lane, o1 = lane + 32;
    int jv0, si0, jv1 = 0, si1 = 8;
    if (o0 < 7)       { jv0 = o0; si0 = 8; }
    else if (o0 < 28) { int q = o0 - 7;  jv0 = 7 + q / 3;  si0 = q % 3; }
    else              { int q = o0 - 28; jv0 = 14 + q / 5; si0 = 3 + q % 5; }
    bool v1ok = o1 < 63;
    if (v1ok) {
        if (o1 < 28) { int q = o1 - 7;  jv1 = 7 + q / 3;  si1 = q % 3; }
        else         { int q = o1 - 28; jv1 = 14 + q / 5; si1 = 3 + q % 5; }
    }

    float acc0 = 0.f, acc1 = 0.f;
    for (int i = 0; i < cnt; i++) {
        int base = start + i;
        int e = g_deid[base];                              // warp-broadcast
        int s = g_desrc[base];
        const float4* eap = (const float4*)(g_ea8 + (size_t)e * 8);
        float4 a0 = __ldg(eap), a1v = __ldg(eap + 1);
        const float* shp = g_sh8 + (size_t)e * 8;
        const float* yb = g_yv + (size_t)s * 168;
        {
            const float4* yp = (const float4*)(yb + jv0 * 8);
            float4 y0 = __ldg(yp), y1 = __ldg(yp + 1);
            float z = a0.x*y0.x + a0.y*y0.y + a0.z*y0.z + a0.w*y0.w
                    + a1v.x*y1.x + a1v.y*y1.y + a1v.z*y1.z;
            float h = (si0 < 8) ? __ldg(shp + si0) : 1.f;
            acc0 = fmaf(z, h, acc0);
        }
        if (v1ok) {
            const float4* yp = (const float4*)(yb + jv1 * 8);
            float4 y0 = __ldg(yp), y1 = __ldg(yp + 1);
            float z = a0.x*y0.x + a0.y*y0.y + a0.z*y0.z + a0.w*y0.w
                    + a1v.x*y1.x + a1v.y*y1.y + a1v.z*y1.z;
            float h = (si1 < 8) ? __ldg(shp + si1) : 1.f;
            acc1 = fmaf(z, h, acc1);
        }
    }
    g_m[(size_t)n * MDIM + o0] = acc0;
    if (v1ok) g_m[(size_t)n * MDIM + o1] = acc1;
    else if (lane == 31) g_m[(size_t)n * MDIM + 63] = 0.f;
}

__device__ __forceinline__ float sel8(float4 a, float4 b, int i) {
    float lo = (i == 0) ? a.x : (i == 1) ? a.y : (i == 2) ? a.z : a.w;
    float hi = (i == 4) ? b.x : (i == 5) ? b.y : (i == 6) ? b.z : b.w;
    return (i < 4) ? lo : hi;
}

// pass2: warp per dst node, lane-per-output, coalesced m loads, ONE final reduce
__global__ void __launch_bounds__(256) k_pass2(
    const int* __restrict__ batch, float* __restrict__ out)
{
    int warp = (blockIdx.x * 256 + threadIdx.x) >> 5;
    int lane = threadIdx.x & 31;
    if (warp >= NN) return;
    int n = warp;
    int start = g_start_d[n];
    int cnt = g_cnt_d[n];

    int o0 = lane, o1 = lane + 32;
    int v0, si0, v1 = 0, si1 = 8;
    if (o0 < 7)       { v0 = o0; si0 = 8; }
    else if (o0 < 28) { int q = o0 - 7;  v0 = q / 3; si0 = q % 3; }
    else              { int q = o0 - 28; v0 = q / 5; si0 = 3 + q % 5; }
    bool v1ok = o1 < 63;
    if (v1ok) {
        if (o1 < 28) { int q = o1 - 7;  v1 = q / 3; si1 = q % 3; }
        else         { int q = o1 - 28; v1 = q / 5; si1 = 3 + q % 5; }
    }

    float acc0 = 0.f, acc1 = 0.f;
    for (int i = 0; i < cnt; i++) {
        int base = start + i;
        int e = g_deid[base];                              // warp-broadcast
        int s = g_desrc[base];
        const float* mrow = g_m + (size_t)s * MDIM;
        const float4* eap = (const float4*)(g_ea8 + (size_t)e * 8);
        float4 e0 = __ldg(eap), e1 = __ldg(eap + 1);
        const float4* shp = (const float4*)(g_sh8 + (size_t)e * 8);
        float4 h0 = __ldg(shp), h1 = __ldg(shp + 1);
        {
            float m = __ldg(mrow + o0);                    // coalesced wavefront
            float a = sel8(e0, e1, v0);
            float h = (si0 < 8) ? sel8(h0, h1, si0) : 1.f;
            acc0 = fmaf(m, a * h, acc0);
        }
        if (v1ok) {
            float m = __ldg(mrow + o1);
            float a = sel8(e0, e1, v1);
            float h = (si1 < 8) ? sel8(h0, h1, si1) : 1.f;
            acc1 = fmaf(m, a * h, acc1);
        }
    }

    float gsum = acc0 + acc1;
#pragma unroll
    for (int off = 16; off > 0; off >>= 1)
        gsum += __shfl_xor_sync(0xffffffffu, gsum, off);
    if (lane == 0) atomicAdd(&out[batch[n]], gsum);
}

extern "C" void kernel_launch(void* const* d_in, const int* in_sizes, int n_in,
                              void* d_out, int out_size) {
    const float* pos   = (const float*)d_in[0];
    const float* x     = (const float*)d_in[1];
    const float* ea    = (const float*)d_in[2];
    const int*   ei    = (const int*)d_in[3];
    const int*   batch = (const int*)d_in[4];
    const float* W1    = (const float*)d_in[5];
    const float* W2    = (const float*)d_in[6];
    const float* W3    = (const float*)d_in[7];
    const float* V1    = (const float*)d_in[8];
    const float* V2    = (const float*)d_in[9];
    const float* V3    = (const float*)d_in[10];
    float* out = (float*)d_out;

    k_zero<<<80, 256>>>(out);
    k_count<<<(NE + 255) / 256, 256>>>(ei);
    k_scan<<<1, 1024>>>();
    k_fill<<<(NE + 255) / 256, 256>>>(ei, ea, pos);
    k_wv<<<7, 512>>>(W1, W2, W3, V1, V2, V3);
    k_yv<<<1480, 160>>>(x);
    k_maccum<<<(NN * 32 + 255) / 256, 256>>>();
    k_pass2<<<(NN * 32 + 255) / 256, 256>>>(batch, out);
}

// round 11
// speedup vs baseline: 1.6100x; 1.4975x over previous
#include <cuda_runtime.h>

#define NN 20000
#define NE 320000
#define NG 256
#define NA 23
#define NB 7
#define M0 64
#define M1 24
#define M2 16
#define MDIM 64

__device__ __align__(16) float g_wv[3381];                 // WV[(jv*7+v)*23 + u]
__device__ __align__(16) float g_yv[(size_t)NN * 168];     // yv[n][jv(21)*8 + v(7)]
__device__ __align__(16) float g_ead[(size_t)NE * 8];      // dst-sorted ea, padded
__device__ __align__(16) float g_shd[(size_t)NE * 8];      // dst-sorted sh1(3),sh2(5)
__device__ __align__(16) float g_m[(size_t)NN * MDIM];
__device__ int g_cnt_d[NN];                                // zeroed by k_scan after read
__device__ int g_cur_d[NN];
__device__ int g_start_d[NN + 1];
__device__ int g_desrc[NE];

#define A1  0.078811041f
#define C0  0.047245559f
#define C1  0.044543540f
#define C2  0.042257713f
#define S3  1.7320508075688772f
#define S5  2.23606797749979f
#define S15 3.872983346207417f

// count edges per dst; also zero the graph output
__global__ void k_count(const int* __restrict__ ei, float* __restrict__ out) {
    int e = blockIdx.x * blockDim.x + threadIdx.x;
    if (e < NG) out[e] = 0.f;
    if (e < NE) atomicAdd(&g_cnt_d[ei[NE + e]], 1);
}

// exclusive scan of cnt -> cur/start; self-cleans cnt back to 0 for next replay
__global__ void __launch_bounds__(1024) k_scan() {
    __shared__ int sums[1024];
    int t = threadIdx.x;
    int base = t * 20;
    int local[20]; int s = 0;
#pragma unroll
    for (int i = 0; i < 20; i++) {
        int idx = base + i;
        int c = 0;
        if (idx < NN) { c = g_cnt_d[idx]; g_cnt_d[idx] = 0; }
        local[i] = s; s += c;
    }
    sums[t] = s;
    __syncthreads();
    for (int d = 1; d < 1024; d <<= 1) {
        int v = (t >= d) ? sums[t - d] : 0;
        __syncthreads();
        if (t >= d) sums[t] += v;
        __syncthreads();
    }
    int excl = (t == 0) ? 0 : sums[t - 1];
#pragma unroll
    for (int i = 0; i < 20; i++) {
        int idx = base + i;
        if (idx < NN) { g_cur_d[idx] = excl + local[i]; g_start_d[idx] = excl + local[i]; }
    }
    if (t == 1023) g_start_d[NN] = sums[1023];
}

// fill: dst-sort edges; stage ea (padded) and sh per edge at dst position
__global__ void k_fill(const int* __restrict__ ei, const float* __restrict__ ea,
                       const float* __restrict__ pos) {
    int e = blockIdx.x * blockDim.x + threadIdx.x;
    if (e >= NE) return;
    int src = ei[e];
    int dst = ei[NE + e];
    int pd = atomicAdd(&g_cur_d[dst], 1);
    g_desrc[pd] = src;

    float a0 = __ldg(ea + e*7 + 0), a1 = __ldg(ea + e*7 + 1);
    float a2 = __ldg(ea + e*7 + 2), a3 = __ldg(ea + e*7 + 3);
    float a4 = __ldg(ea + e*7 + 4), a5 = __ldg(ea + e*7 + 5);
    float a6 = __ldg(ea + e*7 + 6);
    float4* eap = (float4*)(g_ead + (size_t)pd * 8);
    eap[0] = make_float4(a0, a1, a2, a3);
    eap[1] = make_float4(a4, a5, a6, 0.f);

    float px = __ldg(pos + src*3+0) - __ldg(pos + dst*3+0);
    float py = __ldg(pos + src*3+1) - __ldg(pos + dst*3+1);
    float pz = __ldg(pos + src*3+2) - __ldg(pos + dst*3+2);
    float r2 = px*px + py*py + pz*pz;
    float4* shp = (float4*)(g_shd + (size_t)pd * 8);
    shp[0] = make_float4(S3*px, S3*py, S3*pz, S15*px*py);
    shp[1] = make_float4(S15*py*pz, 0.5f*S5*(3.f*pz*pz - r2),
                         S15*px*pz, 0.5f*S15*(px*px - py*py));
}

// WV[(jv*7+v)*23+u] = scale_j * sum_w W_j[u,v,w] * V_j[w, v']
__global__ void k_wv(const float* __restrict__ W1, const float* __restrict__ W2,
                     const float* __restrict__ W3, const float* __restrict__ V1,
                     const float* __restrict__ V2, const float* __restrict__ V3) {
    int o = blockIdx.x * 512 + threadIdx.x;
    if (o >= 3381) return;
    int u = o % 23;
    int t = o / 23;
    int v = t % 7;
    int jv = t / 7;
    int j = jv / 7, vp = jv % 7;
    float r = 0.f;
    if (j == 0) {
        for (int w = 0; w < M0; w++) r = fmaf(W1[(u*7+v)*M0 + w], V1[w*7 + vp], r);
        r *= A1 * C0;
    } else if (j == 1) {
        for (int w = 0; w < M1; w++) r = fmaf(W2[(u*7+v)*M1 + w], V2[w*7 + vp], r);
        r *= A1 * C1;
    } else {
        for (int w = 0; w < M2; w++) r = fmaf(W3[(u*7+v)*M2 + w], V3[w*7 + vp], r);
        r *= A1 * C2;
    }
    g_wv[o] = r;
}

// yv[n, jv*8 + v] = sum_u x[n,u] * WV[(jv*7+v)*23 + u]
__global__ void __launch_bounds__(160) k_yv(const float* __restrict__ x) {
    __shared__ float xs[NA];
    int t = threadIdx.x;
    bool act = t < 147;
    float wreg[NA];
    if (act) {
#pragma unroll
        for (int u = 0; u < NA; u++) wreg[u] = g_wv[t * 23 + u];
    }
    int jv = t / 7, v = t % 7;
    int off = jv * 8 + v;
    for (int n = blockIdx.x; n < NN; n += gridDim.x) {
        __syncthreads();
        if (t < NA) xs[t] = x[n * NA + t];
        __syncthreads();
        if (!act) continue;
        float r = 0.f;
#pragma unroll
        for (int u = 0; u < NA; u++) r = fmaf(xs[u], wreg[u], r);
        g_yv[(size_t)n * 168 + off] = r;
    }
}

// maccum: warp per dst node; m[n,o] = sum_e sh(e,si(o)) * (ea[e,:].yv[src,jv(o),:])
// (R7 structure; manual 2x unroll for MLP)
__global__ void __launch_bounds__(256) k_maccum() {
    int warp = (blockIdx.x * 256 + threadIdx.x) >> 5;
    int lane = threadIdx.x & 31;
    if (warp >= NN) return;
    int n = warp;
    int start = g_start_d[n];
    int cnt = g_start_d[n + 1] - start;

    int o0 = lane, o1 = lane + 32;
    int jv0, si0, jv1 = 0, si1 = 8;
    if (o0 < 7)       { jv0 = o0; si0 = 8; }
    else if (o0 < 28) { int q = o0 - 7;  jv0 = 7 + q / 3;  si0 = q % 3; }
    else              { int q = o0 - 28; jv0 = 14 + q / 5; si0 = 3 + q % 5; }
    bool v1ok = o1 < 63;
    if (v1ok) {
        if (o1 < 28) { int q = o1 - 7;  jv1 = 7 + q / 3;  si1 = q % 3; }
        else         { int q = o1 - 28; jv1 = 14 + q / 5; si1 = 3 + q % 5; }
    }

    float acc0 = 0.f, acc1 = 0.f;

#define MB(ii) { \
    int base = start + (ii); \
    int s = g_desrc[base]; \
    const float4* eap = (const float4*)(g_ead + (size_t)base * 8); \
    float4 a0 = __ldg(eap), a1v = __ldg(eap + 1); \
    const float* shp = g_shd + (size_t)base * 8; \
    const float* yb = g_yv + (size_t)s * 168; \
    { \
        const float4* yp = (const float4*)(yb + jv0 * 8); \
        float4 y0 = __ldg(yp), y1 = __ldg(yp + 1); \
        float z = a0.x*y0.x + a0.y*y0.y + a0.z*y0.z + a0.w*y0.w \
                + a1v.x*y1.x + a1v.y*y1.y + a1v.z*y1.z; \
        float h = (si0 < 8) ? __ldg(shp + si0) : 1.f; \
        acc0 = fmaf(z, h, acc0); \
    } \
    if (v1ok) { \
        const float4* yp = (const float4*)(yb + jv1 * 8); \
        float4 y0 = __ldg(yp), y1 = __ldg(yp + 1); \
        float z = a0.x*y0.x + a0.y*y0.y + a0.z*y0.z + a0.w*y0.w \
                + a1v.x*y1.x + a1v.y*y1.y + a1v.z*y1.z; \
        float h = (si1 < 8) ? __ldg(shp + si1) : 1.f; \
        acc1 = fmaf(z, h, acc1); \
    } \
}

    int i = 0;
    for (; i + 2 <= cnt; i += 2) { MB(i); MB(i + 1); }
    if (i < cnt) { MB(i); }
#undef MB

    g_m[(size_t)n * MDIM + o0] = acc0;
    if (v1ok) g_m[(size_t)n * MDIM + o1] = acc1;
    else if (lane == 31) g_m[(size_t)n * MDIM + 63] = 0.f;
}

// pass2: warp per dst node (R7-identical body); lane strides edges,
// private m-row gather (16 independent LDG.128 per edge -> high MLP)
__global__ void __launch_bounds__(256) k_pass2(
    const int* __restrict__ batch, float* __restrict__ out)
{
    int warp = (blockIdx.x * 256 + threadIdx.x) >> 5;
    int lane = threadIdx.x & 31;
    if (warp >= NN) return;
    int n = warp;
    int start = g_start_d[n];
    int cnt = g_start_d[n + 1] - start;

    float gsum = 0.f;
    for (int i = lane; i < cnt; i += 32) {
        int base = start + i;
        const float4* eap = (const float4*)(g_ead + (size_t)base * 8);
        float4 a0 = __ldg(eap), a1v = __ldg(eap + 1);
        const float4* shp = (const float4*)(g_shd + (size_t)base * 8);
        float4 h0 = __ldg(shp), h1 = __ldg(shp + 1);
        int s = g_desrc[base];

        float eav[NB] = { a0.x, a0.y, a0.z, a0.w, a1v.x, a1v.y, a1v.z };
        float mreg[64];
        const float4* mp = (const float4*)(g_m + (size_t)s * MDIM);
#pragma unroll
        for (int q = 0; q < 16; q++) ((float4*)mreg)[q] = __ldg(mp + q);

        float g = 0.f;
#pragma unroll
        for (int v = 0; v < NB; v++) {
            const float* m1v = mreg + 7 + v * 3;
            const float* m2v = mreg + 28 + v * 5;
            float t = mreg[v];
            t = fmaf(h0.x, m1v[0], t);
            t = fmaf(h0.y, m1v[1], t);
            t = fmaf(h0.z, m1v[2], t);
            t = fmaf(h0.w, m2v[0], t);
            t = fmaf(h1.x, m2v[1], t);
            t = fmaf(h1.y, m2v[2], t);
            t = fmaf(h1.z, m2v[3], t);
            t = fmaf(h1.w, m2v[4], t);
            g = fmaf(eav[v], t, g);
        }
        gsum += g;
    }

#pragma unroll
    for (int off = 16; off > 0; off >>= 1)
        gsum += __shfl_xor_sync(0xFFFFFFFFu, gsum, off);

    if (lane == 0) atomicAdd(&out[batch[n]], gsum);
}

extern "C" void kernel_launch(void* const* d_in, const int* in_sizes, int n_in,
                              void* d_out, int out_size) {
    const float* pos   = (const float*)d_in[0];
    const float* x     = (const float*)d_in[1];
    const float* ea    = (const float*)d_in[2];
    const int*   ei    = (const int*)d_in[3];
    const int*   batch = (const int*)d_in[4];
    const float* W1    = (const float*)d_in[5];
    const float* W2    = (const float*)d_in[6];
    const float* W3    = (const float*)d_in[7];
    const float* V1    = (const float*)d_in[8];
    const float* V2    = (const float*)d_in[9];
    const float* V3    = (const float*)d_in[10];
    float* out = (float*)d_out;

    k_count<<<(NE + 255) / 256, 256>>>(ei, out);
    k_scan<<<1, 1024>>>();
    k_fill<<<(NE + 255) / 256, 256>>>(ei, ea, pos);
    k_wv<<<7, 512>>>(W1, W2, W3, V1, V2, V3);
    k_yv<<<1480, 160>>>(x);
    k_maccum<<<(NN * 32 + 255) / 256, 256>>>();
    k_pass2<<<(NN * 32 + 255) / 256, 256>>>(batch, out);
}

// round 12
// speedup vs baseline: 1.8324x; 1.1381x over previous
#include <cuda_runtime.h>

#define NN 20000
#define NE 320000
#define NG 256
#define NA 23
#define NB 7
#define M0 64
#define M1 24
#define M2 16
#define MDIM 64

#define CNT_BLOCKS ((NE + 255) / 256)        // 1250
#define WV_WARPS 3381
#define WV_BLOCKS ((WV_WARPS * 32 + 255) / 256)  // 423

__device__ __align__(16) float g_wv[3381];                 // WV[(jv*7+v)*23 + u]
__device__ __align__(16) float g_yv[(size_t)NN * 168];     // yv[n][jv(21)*8 + v(7)]
__device__ __align__(16) float g_ead[(size_t)NE * 8];      // dst-sorted ea, padded
__device__ __align__(16) float g_shd[(size_t)NE * 8];      // dst-sorted sh1(3),sh2(5)
__device__ __align__(16) float g_m[(size_t)NN * MDIM];
__device__ int g_cnt_d[NN];                                // zeroed by k_scan after read
__device__ int g_cur_d[NN];
__device__ int g_start_d[NN + 1];
__device__ int g_desrc[NE];

#define A1  0.078811041f
#define C0  0.047245559f
#define C1  0.044543540f
#define C2  0.042257713f
#define S3  1.7320508075688772f
#define S5  2.23606797749979f
#define S15 3.872983346207417f

// merged: blocks [0, CNT_BLOCKS) count edges per dst + zero out;
//         blocks [CNT_BLOCKS, +WV_BLOCKS) compute WV warp-per-output.
__global__ void k_count_wv(const int* __restrict__ ei, float* __restrict__ out,
                           const float* __restrict__ W1, const float* __restrict__ W2,
                           const float* __restrict__ W3, const float* __restrict__ V1,
                           const float* __restrict__ V2, const float* __restrict__ V3) {
    if (blockIdx.x < CNT_BLOCKS) {
        int e = blockIdx.x * blockDim.x + threadIdx.x;
        if (e < NG) out[e] = 0.f;
        if (e < NE) atomicAdd(&g_cnt_d[ei[NE + e]], 1);
        return;
    }
    // WV[(jv*7+v)*23+u] = scale_j * sum_w W_j[u,v,w] * V_j[w, v']
    int wid = (blockIdx.x - CNT_BLOCKS) * 8 + (threadIdx.x >> 5);
    int lane = threadIdx.x & 31;
    if (wid >= WV_WARPS) return;
    int o = wid;
    int u = o % 23;
    int t = o / 23;
    int v = t % 7;
    int jv = t / 7;
    int j = jv / 7, vp = jv % 7;

    float r = 0.f;
    if (j == 0) {
        // M0 = 64: lanes cover w = lane, lane+32
        r = W1[(u*7+v)*M0 + lane] * V1[lane*7 + vp]
          + W1[(u*7+v)*M0 + lane + 32] * V1[(lane+32)*7 + vp];
    } else if (j == 1) {
        if (lane < M1) r = W2[(u*7+v)*M1 + lane] * V2[lane*7 + vp];
    } else {
        if (lane < M2) r = W3[(u*7+v)*M2 + lane] * V3[lane*7 + vp];
    }
#pragma unroll
    for (int off = 16; off > 0; off >>= 1)
        r += __shfl_xor_sync(0xffffffffu, r, off);
    if (lane == 0) {
        float sc = (j == 0) ? (A1 * C0) : (j == 1) ? (A1 * C1) : (A1 * C2);
        g_wv[o] = r * sc;
    }
}

// exclusive scan of cnt -> cur/start; self-cleans cnt back to 0 for next replay
__global__ void __launch_bounds__(1024) k_scan() {
    __shared__ int sums[1024];
    int t = threadIdx.x;
    int base = t * 20;
    int local[20]; int s = 0;
#pragma unroll
    for (int i = 0; i < 20; i++) {
        int idx = base + i;
        int c = 0;
        if (idx < NN) { c = g_cnt_d[idx]; g_cnt_d[idx] = 0; }
        local[i] = s; s += c;
    }
    sums[t] = s;
    __syncthreads();
    for (int d = 1; d < 1024; d <<= 1) {
        int v = (t >= d) ? sums[t - d] : 0;
        __syncthreads();
        if (t >= d) sums[t] += v;
        __syncthreads();
    }
    int excl = (t == 0) ? 0 : sums[t - 1];
#pragma unroll
    for (int i = 0; i < 20; i++) {
        int idx = base + i;
        if (idx < NN) { g_cur_d[idx] = excl + local[i]; g_start_d[idx] = excl + local[i]; }
    }
    if (t == 1023) g_start_d[NN] = sums[1023];
}

// fill: dst-sort edges; stage ea (padded) and sh per edge at dst position
__global__ void k_fill(const int* __restrict__ ei, const float* __restrict__ ea,
                       const float* __restrict__ pos) {
    int e = blockIdx.x * blockDim.x + threadIdx.x;
    if (e >= NE) return;
    int src = ei[e];
    int dst = ei[NE + e];
    int pd = atomicAdd(&g_cur_d[dst], 1);
    g_desrc[pd] = src;

    float a0 = __ldg(ea + e*7 + 0), a1 = __ldg(ea + e*7 + 1);
    float a2 = __ldg(ea + e*7 + 2), a3 = __ldg(ea + e*7 + 3);
    float a4 = __ldg(ea + e*7 + 4), a5 = __ldg(ea + e*7 + 5);
    float a6 = __ldg(ea + e*7 + 6);
    float4* eap = (float4*)(g_ead + (size_t)pd * 8);
    eap[0] = make_float4(a0, a1, a2, a3);
    eap[1] = make_float4(a4, a5, a6, 0.f);

    float px = __ldg(pos + src*3+0) - __ldg(pos + dst*3+0);
    float py = __ldg(pos + src*3+1) - __ldg(pos + dst*3+1);
    float pz = __ldg(pos + src*3+2) - __ldg(pos + dst*3+2);
    float r2 = px*px + py*py + pz*pz;
    float4* shp = (float4*)(g_shd + (size_t)pd * 8);
    shp[0] = make_float4(S3*px, S3*py, S3*pz, S15*px*py);
    shp[1] = make_float4(S15*py*pz, 0.5f*S5*(3.f*pz*pz - r2),
                         S15*px*pz, 0.5f*S15*(px*px - py*py));
}

// yv[n, jv*8 + v] = sum_u x[n,u] * WV[(jv*7+v)*23 + u]
__global__ void __launch_bounds__(160) k_yv(const float* __restrict__ x) {
    __shared__ float xs[NA];
    int t = threadIdx.x;
    bool act = t < 147;
    float wreg[NA];
    if (act) {
#pragma unroll
        for (int u = 0; u < NA; u++) wreg[u] = g_wv[t * 23 + u];
    }
    int jv = t / 7, v = t % 7;
    int off = jv * 8 + v;
    for (int n = blockIdx.x; n < NN; n += gridDim.x) {
        __syncthreads();
        if (t < NA) xs[t] = x[n * NA + t];
        __syncthreads();
        if (!act) continue;
        float r = 0.f;
#pragma unroll
        for (int u = 0; u < NA; u++) r = fmaf(xs[u], wreg[u], r);
        g_yv[(size_t)n * 168 + off] = r;
    }
}

// maccum: warp per dst node; m[n,o] = sum_e sh(e,si(o)) * (ea[e,:].yv[src,jv(o),:])
__global__ void __launch_bounds__(256) k_maccum() {
    int warp = (blockIdx.x * 256 + threadIdx.x) >> 5;
    int lane = threadIdx.x & 31;
    if (warp >= NN) return;
    int n = warp;
    int start = g_start_d[n];
    int cnt = g_start_d[n + 1] - start;

    int o0 = lane, o1 = lane + 32;
    int jv0, si0, jv1 = 0, si1 = 8;
    if (o0 < 7)       { jv0 = o0; si0 = 8; }
    else if (o0 < 28) { int q = o0 - 7;  jv0 = 7 + q / 3;  si0 = q % 3; }
    else              { int q = o0 - 28; jv0 = 14 + q / 5; si0 = 3 + q % 5; }
    bool v1ok = o1 < 63;
    if (v1ok) {
        if (o1 < 28) { int q = o1 - 7;  jv1 = 7 + q / 3;  si1 = q % 3; }
        else         { int q = o1 - 28; jv1 = 14 + q / 5; si1 = 3 + q % 5; }
    }

    float acc0 = 0.f, acc1 = 0.f;

#define MB(ii) { \
    int base = start + (ii); \
    int s = g_desrc[base]; \
    const float4* eap = (const float4*)(g_ead + (size_t)base * 8); \
    float4 a0 = __ldg(eap), a1v = __ldg(eap + 1); \
    const float* shp = g_shd + (size_t)base * 8; \
    const float* yb = g_yv + (size_t)s * 168; \
    { \
        const float4* yp = (const float4*)(yb + jv0 * 8); \
        float4 y0 = __ldg(yp), y1 = __ldg(yp + 1); \
        float z = a0.x*y0.x + a0.y*y0.y + a0.z*y0.z + a0.w*y0.w \
                + a1v.x*y1.x + a1v.y*y1.y + a1v.z*y1.z; \
        float h = (si0 < 8) ? __ldg(shp + si0) : 1.f; \
        acc0 = fmaf(z, h, acc0); \
    } \
    if (v1ok) { \
        const float4* yp = (const float4*)(yb + jv1 * 8); \
        float4 y0 = __ldg(yp), y1 = __ldg(yp + 1); \
        float z = a0.x*y0.x + a0.y*y0.y + a0.z*y0.z + a0.w*y0.w \
                + a1v.x*y1.x + a1v.y*y1.y + a1v.z*y1.z; \
        float h = (si1 < 8) ? __ldg(shp + si1) : 1.f; \
        acc1 = fmaf(z, h, acc1); \
    } \
}

    int i = 0;
    for (; i + 2 <= cnt; i += 2) { MB(i); MB(i + 1); }
    if (i < cnt) { MB(i); }
#undef MB

    g_m[(size_t)n * MDIM + o0] = acc0;
    if (v1ok) g_m[(size_t)n * MDIM + o1] = acc1;
    else if (lane == 31) g_m[(size_t)n * MDIM + 63] = 0.f;
}

// pass2: warp per dst node; lane strides edges, private m-row gather
__global__ void __launch_bounds__(256) k_pass2(
    const int* __restrict__ batch, float* __restrict__ out)
{
    int warp = (blockIdx.x * 256 + threadIdx.x) >> 5;
    int lane = threadIdx.x & 31;
    if (warp >= NN) return;
    int n = warp;
    int start = g_start_d[n];
    int cnt = g_start_d[n + 1] - start;

    float gsum = 0.f;
    for (int i = lane; i < cnt; i += 32) {
        int base = start + i;
        const float4* eap = (const float4*)(g_ead + (size_t)base * 8);
        float4 a0 = __ldg(eap), a1v = __ldg(eap + 1);
        const float4* shp = (const float4*)(g_shd + (size_t)base * 8);
        float4 h0 = __ldg(shp), h1 = __ldg(shp + 1);
        int s = g_desrc[base];

        float eav[NB] = { a0.x, a0.y, a0.z, a0.w, a1v.x, a1v.y, a1v.z };
        float mreg[64];
        const float4* mp = (const float4*)(g_m + (size_t)s * MDIM);
#pragma unroll
        for (int q = 0; q < 16; q++) ((float4*)mreg)[q] = __ldg(mp + q);

        float g = 0.f;
#pragma unroll
        for (int v = 0; v < NB; v++) {
            const float* m1v = mreg + 7 + v * 3;
            const float* m2v = mreg + 28 + v * 5;
            float t = mreg[v];
            t = fmaf(h0.x, m1v[0], t);
            t = fmaf(h0.y, m1v[1], t);
            t = fmaf(h0.z, m1v[2], t);
            t = fmaf(h0.w, m2v[0], t);
            t = fmaf(h1.x, m2v[1], t);
            t = fmaf(h1.y, m2v[2], t);
            t = fmaf(h1.z, m2v[3], t);
            t = fmaf(h1.w, m2v[4], t);
            g = fmaf(eav[v], t, g);
        }
        gsum += g;
    }

#pragma unroll
    for (int off = 16; off > 0; off >>= 1)
        gsum += __shfl_xor_sync(0xFFFFFFFFu, gsum, off);

    if (lane == 0) atomicAdd(&out[batch[n]], gsum);
}

extern "C" void kernel_launch(void* const* d_in, const int* in_sizes, int n_in,
                              void* d_out, int out_size) {
    const float* pos   = (const float*)d_in[0];
    const float* x     = (const float*)d_in[1];
    const float* ea    = (const float*)d_in[2];
    const int*   ei    = (const int*)d_in[3];
    const int*   batch = (const int*)d_in[4];
    const float* W1    = (const float*)d_in[5];
    const float* W2    = (const float*)d_in[6];
    const float* W3    = (const float*)d_in[7];
    const float* V1    = (const float*)d_in[8];
    const float* V2    = (const float*)d_in[9];
    const float* V3    = (const float*)d_in[10];
    float* out = (float*)d_out;

    k_count_wv<<<CNT_BLOCKS + WV_BLOCKS, 256>>>(ei, out, W1, W2, W3, V1, V2, V3);
    k_scan<<<1, 1024>>>();
    k_fill<<<(NE + 255) / 256, 256>>>(ei, ea, pos);
    k_yv<<<1480, 160>>>(x);
    k_maccum<<<(NN * 32 + 255) / 256, 256>>>();
    k_pass2<<<(NN * 32 + 255) / 256, 256>>>(batch, out);
}

// round 13
// speedup vs baseline: 1.9310x; 1.0538x over previous
#include <cuda_runtime.h>

#define NN 20000
#define NE 320000
#define NG 256
#define NA 23
#define NB 7
#define M0 64
#define M1 24
#define M2 16
#define MDIM 64

#define CNT_BLOCKS ((NE + 255) / 256)            // 1250
#define WV_WARPS 3381
#define WV_BLOCKS ((WV_WARPS + 7) / 8)           // 423 (8 warps/block)
#define FILL_BLOCKS ((NE + 255) / 256)           // 1250
#define YV_BLOCKS 1000
#define YV_CHUNKS (NN / 8)                       // 2500

__device__ __align__(16) float g_wv[3381];                 // WV[(jv*7+v)*23 + u]
__device__ __align__(16) float g_yv[(size_t)NN * 168];     // yv[n][jv(21)*8 + v(7)]
__device__ __align__(16) float g_ead[(size_t)NE * 8];      // dst-sorted ea, padded
__device__ __align__(16) float g_shd[(size_t)NE * 8];      // dst-sorted sh1(3),sh2(5)
__device__ __align__(16) float g_m[(size_t)NN * MDIM];
__device__ int g_cnt_d[NN];                                // zeroed by k_scan after read
__device__ int g_cur_d[NN];
__device__ int g_start_d[NN + 1];
__device__ int g_desrc[NE];

#define A1  0.078811041f
#define C0  0.047245559f
#define C1  0.044543540f
#define C2  0.042257713f
#define S3  1.7320508075688772f
#define S5  2.23606797749979f
#define S15 3.872983346207417f

// merged: blocks [0, CNT_BLOCKS): count edges per dst + zero out;
//         blocks [CNT_BLOCKS, +WV_BLOCKS): WV warp-per-output.
__global__ void k_count_wv(const int* __restrict__ ei, float* __restrict__ out,
                           const float* __restrict__ W1, const float* __restrict__ W2,
                           const float* __restrict__ W3, const float* __restrict__ V1,
                           const float* __restrict__ V2, const float* __restrict__ V3) {
    if (blockIdx.x < CNT_BLOCKS) {
        int e = blockIdx.x * blockDim.x + threadIdx.x;
        if (e < NG) out[e] = 0.f;
        if (e < NE) atomicAdd(&g_cnt_d[ei[NE + e]], 1);
        return;
    }
    int wid = (blockIdx.x - CNT_BLOCKS) * 8 + (threadIdx.x >> 5);
    int lane = threadIdx.x & 31;
    if (wid >= WV_WARPS) return;
    int o = wid;
    int u = o % 23;
    int t = o / 23;
    int v = t % 7;
    int jv = t / 7;
    int j = jv / 7, vp = jv % 7;

    float r = 0.f;
    if (j == 0) {
        r = W1[(u*7+v)*M0 + lane] * V1[lane*7 + vp]
          + W1[(u*7+v)*M0 + lane + 32] * V1[(lane+32)*7 + vp];
    } else if (j == 1) {
        if (lane < M1) r = W2[(u*7+v)*M1 + lane] * V2[lane*7 + vp];
    } else {
        if (lane < M2) r = W3[(u*7+v)*M2 + lane] * V3[lane*7 + vp];
    }
#pragma unroll
    for (int off = 16; off > 0; off >>= 1)
        r += __shfl_xor_sync(0xffffffffu, r, off);
    if (lane == 0) {
        float sc = (j == 0) ? (A1 * C0) : (j == 1) ? (A1 * C1) : (A1 * C2);
        g_wv[o] = r * sc;
    }
}

// exclusive scan of cnt -> cur/start; self-cleans cnt back to 0 for next replay
__global__ void __launch_bounds__(1024) k_scan() {
    __shared__ int sums[1024];
    int t = threadIdx.x;
    int base = t * 20;
    int local[20]; int s = 0;
#pragma unroll
    for (int i = 0; i < 20; i++) {
        int idx = base + i;
        int c = 0;
        if (idx < NN) { c = g_cnt_d[idx]; g_cnt_d[idx] = 0; }
        local[i] = s; s += c;
    }
    sums[t] = s;
    __syncthreads();
    for (int d = 1; d < 1024; d <<= 1) {
        int v = (t >= d) ? sums[t - d] : 0;
        __syncthreads();
        if (t >= d) sums[t] += v;
        __syncthreads();
    }
    int excl = (t == 0) ? 0 : sums[t - 1];
#pragma unroll
    for (int i = 0; i < 20; i++) {
        int idx = base + i;
        if (idx < NN) { g_cur_d[idx] = excl + local[i]; g_start_d[idx] = excl + local[i]; }
    }
    if (t == 1023) g_start_d[NN] = sums[1023];
}

// merged: blocks [0, FILL_BLOCKS): dst-sort + stage ea/sh;
//         blocks [FILL_BLOCKS, +YV_BLOCKS): yv, 8 nodes per barrier.
__global__ void __launch_bounds__(256) k_fill_yv(
    const int* __restrict__ ei, const float* __restrict__ ea,
    const float* __restrict__ pos, const float* __restrict__ x)
{
    if (blockIdx.x < FILL_BLOCKS) {
        int e = blockIdx.x * 256 + threadIdx.x;
        if (e >= NE) return;
        int src = ei[e];
        int dst = ei[NE + e];
        int pd = atomicAdd(&g_cur_d[dst], 1);
        g_desrc[pd] = src;

        float a0 = __ldg(ea + e*7 + 0), a1 = __ldg(ea + e*7 + 1);
        float a2 = __ldg(ea + e*7 + 2), a3 = __ldg(ea + e*7 + 3);
        float a4 = __ldg(ea + e*7 + 4), a5 = __ldg(ea + e*7 + 5);
        float a6 = __ldg(ea + e*7 + 6);
        float4* eap = (float4*)(g_ead + (size_t)pd * 8);
        eap[0] = make_float4(a0, a1, a2, a3);
        eap[1] = make_float4(a4, a5, a6, 0.f);

        float px = __ldg(pos + src*3+0) - __ldg(pos + dst*3+0);
        float py = __ldg(pos + src*3+1) - __ldg(pos + dst*3+1);
        float pz = __ldg(pos + src*3+2) - __ldg(pos + dst*3+2);
        float r2 = px*px + py*py + pz*pz;
        float4* shp = (float4*)(g_shd + (size_t)pd * 8);
        shp[0] = make_float4(S3*px, S3*py, S3*pz, S15*px*py);
        shp[1] = make_float4(S15*py*pz, 0.5f*S5*(3.f*pz*pz - r2),
                             S15*px*pz, 0.5f*S15*(px*px - py*py));
        return;
    }

    // ---- yv branch: 8 nodes per chunk, one barrier per chunk ----
    __shared__ float xs[8 * NA];   // 184 floats, contiguous rows of x
    int t = threadIdx.x;
    bool act = t < 147;
    float wreg[NA];
    if (act) {
#pragma unroll
        for (int u = 0; u < NA; u++) wreg[u] = g_wv[t * 23 + u];
    }
    int jv = t / 7, v = t % 7;
    int off = jv * 8 + v;

    for (int c = blockIdx.x - FILL_BLOCKS; c < YV_CHUNKS; c += YV_BLOCKS) {
        int n0 = c * 8;
        __syncthreads();
        if (t < 8 * NA) xs[t] = x[n0 * NA + t];   // coalesced
        __syncthreads();
        if (!act) continue;
        float acc[8];
#pragma unroll
        for (int k = 0; k < 8; k++) acc[k] = 0.f;
#pragma unroll
        for (int u = 0; u < NA; u++) {
            float w = wreg[u];
#pragma unroll
            for (int k = 0; k < 8; k++)
                acc[k] = fmaf(xs[k * NA + u], w, acc[k]);
        }
#pragma unroll
        for (int k = 0; k < 8; k++)
            g_yv[(size_t)(n0 + k) * 168 + off] = acc[k];
    }
}

// maccum: warp per dst node; m[n,o] = sum_e sh(e,si(o)) * (ea[e,:].yv[src,jv(o),:])
__global__ void __launch_bounds__(256) k_maccum() {
    int warp = (blockIdx.x * 256 + threadIdx.x) >> 5;
    int lane = threadIdx.x & 31;
    if (warp >= NN) return;
    int n = warp;
    int start = g_start_d[n];
    int cnt = g_start_d[n + 1] - start;

    int o0 = lane, o1 = lane + 32;
    int jv0, si0, jv1 = 0, si1 = 8;
    if (o0 < 7)       { jv0 = o0; si0 = 8; }
    else if (o0 < 28) { int q = o0 - 7;  jv0 = 7 + q / 3;  si0 = q % 3; }
    else              { int q = o0 - 28; jv0 = 14 + q / 5; si0 = 3 + q % 5; }
    bool v1ok = o1 < 63;
    if (v1ok) {
        if (o1 < 28) { int q = o1 - 7;  jv1 = 7 + q / 3;  si1 = q % 3; }
        else         { int q = o1 - 28; jv1 = 14 + q / 5; si1 = 3 + q % 5; }
    }

    float acc0 = 0.f, acc1 = 0.f;

#define MB(ii) { \
    int base = start + (ii); \
    int s = g_desrc[base]; \
    const float4* eap = (const float4*)(g_ead + (size_t)base * 8); \
    float4 a0 = __ldg(eap), a1v = __ldg(eap + 1); \
    const float* shp = g_shd + (size_t)base * 8; \
    const float* yb = g_yv + (size_t)s * 168; \
    { \
        const float4* yp = (const float4*)(yb + jv0 * 8); \
        float4 y0 = __ldg(yp), y1 = __ldg(yp + 1); \
        float z = a0.x*y0.x + a0.y*y0.y + a0.z*y0.z + a0.w*y0.w \
                + a1v.x*y1.x + a1v.y*y1.y + a1v.z*y1.z; \
        float h = (si0 < 8) ? __ldg(shp + si0) : 1.f; \
        acc0 = fmaf(z, h, acc0); \
    } \
    if (v1ok) { \
        const float4* yp = (const float4*)(yb + jv1 * 8); \
        float4 y0 = __ldg(yp), y1 = __ldg(yp + 1); \
        float z = a0.x*y0.x + a0.y*y0.y + a0.z*y0.z + a0.w*y0.w \
                + a1v.x*y1.x + a1v.y*y1.y + a1v.z*y1.z; \
        float h = (si1 < 8) ? __ldg(shp + si1) : 1.f; \
        acc1 = fmaf(z, h, acc1); \
    } \
}

    int i = 0;
    for (; i + 2 <= cnt; i += 2) { MB(i); MB(i + 1); }
    if (i < cnt) { MB(i); }
#undef MB

    g_m[(size_t)n * MDIM + o0] = acc0;
    if (v1ok) g_m[(size_t)n * MDIM + o1] = acc1;
    else if (lane == 31) g_m[(size_t)n * MDIM + 63] = 0.f;
}

// pass2: warp per dst node; lane strides edges, private m-row gather
__global__ void __launch_bounds__(256) k_pass2(
    const int* __restrict__ batch, float* __restrict__ out)
{
    int warp = (blockIdx.x * 256 + threadIdx.x) >> 5;
    int lane = threadIdx.x & 31;
    if (warp >= NN) return;
    int n = warp;
    int start = g_start_d[n];
    int cnt = g_start_d[n + 1] - start;

    float gsum = 0.f;
    for (int i = lane; i < cnt; i += 32) {
        int base = start + i;
        const float4* eap = (const float4*)(g_ead + (size_t)base * 8);
        float4 a0 = __ldg(eap), a1v = __ldg(eap + 1);
        const float4* shp = (const float4*)(g_shd + (size_t)base * 8);
        float4 h0 = __ldg(shp), h1 = __ldg(shp + 1);
        int s = g_desrc[base];

        float eav[NB] = { a0.x, a0.y, a0.z, a0.w, a1v.x, a1v.y, a1v.z };
        float mreg[64];
        const float4* mp = (const float4*)(g_m + (size_t)s * MDIM);
#pragma unroll
        for (int q = 0; q < 16; q++) ((float4*)mreg)[q] = __ldg(mp + q);

        float g = 0.f;
#pragma unroll
        for (int v = 0; v < NB; v++) {
            const float* m1v = mreg + 7 + v * 3;
            const float* m2v = mreg + 28 + v * 5;
            float t = mreg[v];
            t = fmaf(h0.x, m1v[0], t);
            t = fmaf(h0.y, m1v[1], t);
            t = fmaf(h0.z, m1v[2], t);
            t = fmaf(h0.w, m2v[0], t);
            t = fmaf(h1.x, m2v[1], t);
            t = fmaf(h1.y, m2v[2], t);
            t = fmaf(h1.z, m2v[3], t);
            t = fmaf(h1.w, m2v[4], t);
            g = fmaf(eav[v], t, g);
        }
        gsum += g;
    }

#pragma unroll
    for (int off = 16; off > 0; off >>= 1)
        gsum += __shfl_xor_sync(0xFFFFFFFFu, gsum, off);

    if (lane == 0) atomicAdd(&out[batch[n]], gsum);
}

extern "C" void kernel_launch(void* const* d_in, const int* in_sizes, int n_in,
                              void* d_out, int out_size) {
    const float* pos   = (const float*)d_in[0];
    const float* x     = (const float*)d_in[1];
    const float* ea    = (const float*)d_in[2];
    const int*   ei    = (const int*)d_in[3];
    const int*   batch = (const int*)d_in[4];
    const float* W1    = (const float*)d_in[5];
    const float* W2    = (const float*)d_in[6];
    const float* W3    = (const float*)d_in[7];
    const float* V1    = (const float*)d_in[8];
    const float* V2    = (const float*)d_in[9];
    const float* V3    = (const float*)d_in[10];
    float* out = (float*)d_out;

    k_count_wv<<<CNT_BLOCKS + WV_BLOCKS, 256>>>(ei, out, W1, W2, W3, V1, V2, V3);
    k_scan<<<1, 1024>>>();
    k_fill_yv<<<FILL_BLOCKS + YV_BLOCKS, 256>>>(ei, ea, pos, x);
    k_maccum<<<(NN * 32 + 255) / 256, 256>>>();
    k_pass2<<<(NN * 32 + 255) / 256, 256>>>(batch, out);
}

// round 14
// speedup vs baseline: 2.0086x; 1.0402x over previous
#include <cuda_runtime.h>

#define NN 20000
#define NE 320000
#define NG 256
#define NA 23
#define NB 7
#define M0 64
#define M1 24
#define M2 16
#define MDIM 64

#define CNT_BLOCKS ((NE + 255) / 256)            // 1250
#define WV_WARPS 3381
#define WV_BLOCKS ((WV_WARPS + 7) / 8)           // 423 (8 warps/block)
#define FILL_BLOCKS ((NE + 255) / 256)           // 1250
#define YV_BLOCKS 1000
#define YV_CHUNKS (NN / 8)                       // 2500

__device__ __align__(16) float g_wv[3381];                 // WV[(jv*7+v)*23 + u]
__device__ __align__(16) float g_yv[(size_t)NN * 168];     // yv[n][jv(21)*8 + v(7)]
__device__ __align__(16) float g_ead[(size_t)NE * 8];      // dst-sorted ea, padded
__device__ __align__(16) float g_shd[(size_t)NE * 8];      // dst-sorted sh1(3),sh2(5)
__device__ __align__(16) float g_m[(size_t)NN * MDIM];
__device__ int g_cnt_d[NN];                                // zeroed by k_scan after read
__device__ int g_cur_d[NN];
__device__ int g_start_d[NN + 1];
__device__ int g_desrc[NE];

#define A1  0.078811041f
#define C0  0.047245559f
#define C1  0.044543540f
#define C2  0.042257713f
#define S3  1.7320508075688772f
#define S5  2.23606797749979f
#define S15 3.872983346207417f

// merged: blocks [0, CNT_BLOCKS): count edges per dst + zero out;
//         blocks [CNT_BLOCKS, +WV_BLOCKS): WV warp-per-output.
__global__ void k_count_wv(const int* __restrict__ ei, float* __restrict__ out,
                           const float* __restrict__ W1, const float* __restrict__ W2,
                           const float* __restrict__ W3, const float* __restrict__ V1,
                           const float* __restrict__ V2, const float* __restrict__ V3) {
    if (blockIdx.x < CNT_BLOCKS) {
        int e = blockIdx.x * blockDim.x + threadIdx.x;
        if (e < NG) out[e] = 0.f;
        if (e < NE) atomicAdd(&g_cnt_d[ei[NE + e]], 1);
        return;
    }
    int wid = (blockIdx.x - CNT_BLOCKS) * 8 + (threadIdx.x >> 5);
    int lane = threadIdx.x & 31;
    if (wid >= WV_WARPS) return;
    int o = wid;
    int u = o % 23;
    int t = o / 23;
    int v = t % 7;
    int jv = t / 7;
    int j = jv / 7, vp = jv % 7;

    float r = 0.f;
    if (j == 0) {
        r = W1[(u*7+v)*M0 + lane] * V1[lane*7 + vp]
          + W1[(u*7+v)*M0 + lane + 32] * V1[(lane+32)*7 + vp];
    } else if (j == 1) {
        if (lane < M1) r = W2[(u*7+v)*M1 + lane] * V2[lane*7 + vp];
    } else {
        if (lane < M2) r = W3[(u*7+v)*M2 + lane] * V3[lane*7 + vp];
    }
#pragma unroll
    for (int off = 16; off > 0; off >>= 1)
        r += __shfl_xor_sync(0xffffffffu, r, off);
    if (lane == 0) {
        float sc = (j == 0) ? (A1 * C0) : (j == 1) ? (A1 * C1) : (A1 * C2);
        g_wv[o] = r * sc;
    }
}

// exclusive scan of cnt -> cur/start; self-cleans cnt back to 0 for next replay
__global__ void __launch_bounds__(1024) k_scan() {
    __shared__ int sums[1024];
    int t = threadIdx.x;
    int base = t * 20;
    int local[20]; int s = 0;
#pragma unroll
    for (int i = 0; i < 20; i++) {
        int idx = base + i;
        int c = 0;
        if (idx < NN) { c = g_cnt_d[idx]; g_cnt_d[idx] = 0; }
        local[i] = s; s += c;
    }
    sums[t] = s;
    __syncthreads();
    for (int d = 1; d < 1024; d <<= 1) {
        int v = (t >= d) ? sums[t - d] : 0;
        __syncthreads();
        if (t >= d) sums[t] += v;
        __syncthreads();
    }
    int excl = (t == 0) ? 0 : sums[t - 1];
#pragma unroll
    for (int i = 0; i < 20; i++) {
        int idx = base + i;
        if (idx < NN) { g_cur_d[idx] = excl + local[i]; g_start_d[idx] = excl + local[i]; }
    }
    if (t == 1023) g_start_d[NN] = sums[1023];
}

// merged: blocks [0, FILL_BLOCKS): dst-sort + stage ea/sh;
//         blocks [FILL_BLOCKS, +YV_BLOCKS): yv, 8 nodes per barrier.
__global__ void __launch_bounds__(256) k_fill_yv(
    const int* __restrict__ ei, const float* __restrict__ ea,
    const float* __restrict__ pos, const float* __restrict__ x)
{
    if (blockIdx.x < FILL_BLOCKS) {
        int e = blockIdx.x * 256 + threadIdx.x;
        if (e >= NE) return;
        int src = ei[e];
        int dst = ei[NE + e];
        int pd = atomicAdd(&g_cur_d[dst], 1);
        g_desrc[pd] = src;

        float a0 = __ldg(ea + e*7 + 0), a1 = __ldg(ea + e*7 + 1);
        float a2 = __ldg(ea + e*7 + 2), a3 = __ldg(ea + e*7 + 3);
        float a4 = __ldg(ea + e*7 + 4), a5 = __ldg(ea + e*7 + 5);
        float a6 = __ldg(ea + e*7 + 6);
        float4* eap = (float4*)(g_ead + (size_t)pd * 8);
        eap[0] = make_float4(a0, a1, a2, a3);
        eap[1] = make_float4(a4, a5, a6, 0.f);

        float px = __ldg(pos + src*3+0) - __ldg(pos + dst*3+0);
        float py = __ldg(pos + src*3+1) - __ldg(pos + dst*3+1);
        float pz = __ldg(pos + src*3+2) - __ldg(pos + dst*3+2);
        float r2 = px*px + py*py + pz*pz;
        float4* shp = (float4*)(g_shd + (size_t)pd * 8);
        shp[0] = make_float4(S3*px, S3*py, S3*pz, S15*px*py);
        shp[1] = make_float4(S15*py*pz, 0.5f*S5*(3.f*pz*pz - r2),
                             S15*px*pz, 0.5f*S15*(px*px - py*py));
        return;
    }

    // ---- yv branch: 8 nodes per chunk, one barrier per chunk ----
    __shared__ float xs[8 * NA];   // 184 floats, contiguous rows of x
    int t = threadIdx.x;
    bool act = t < 147;
    float wreg[NA];
    if (act) {
#pragma unroll
        for (int u = 0; u < NA; u++) wreg[u] = g_wv[t * 23 + u];
    }
    int jv = t / 7, v = t % 7;
    int off = jv * 8 + v;

    for (int c = blockIdx.x - FILL_BLOCKS; c < YV_CHUNKS; c += YV_BLOCKS) {
        int n0 = c * 8;
        __syncthreads();
        if (t < 8 * NA) xs[t] = x[n0 * NA + t];   // coalesced
        __syncthreads();
        if (!act) continue;
        float acc[8];
#pragma unroll
        for (int k = 0; k < 8; k++) acc[k] = 0.f;
#pragma unroll
        for (int u = 0; u < NA; u++) {
            float w = wreg[u];
#pragma unroll
            for (int k = 0; k < 8; k++)
                acc[k] = fmaf(xs[k * NA + u], w, acc[k]);
        }
#pragma unroll
        for (int k = 0; k < 8; k++)
            g_yv[(size_t)(n0 + k) * 168 + off] = acc[k];
    }
}

// maccum: warp per dst node. Lanes 0-20 compute z[jv] ONCE each from a
// coalesced yv row load; shuffles distribute z to the 63 output lanes.
__global__ void __launch_bounds__(256) k_maccum() {
    int warp = (blockIdx.x * 256 + threadIdx.x) >> 5;
    int lane = threadIdx.x & 31;
    if (warp >= NN) return;
    int n = warp;
    int start = g_start_d[n];
    int cnt = g_start_d[n + 1] - start;

    int o0 = lane, o1 = lane + 32;
    int jv0, si0, jv1 = 0, si1 = 8;
    if (o0 < 7)       { jv0 = o0; si0 = 8; }
    else if (o0 < 28) { int q = o0 - 7;  jv0 = 7 + q / 3;  si0 = q % 3; }
    else              { int q = o0 - 28; jv0 = 14 + q / 5; si0 = 3 + q % 5; }
    bool v1ok = o1 < 63;
    if (v1ok) {
        if (o1 < 28) { int q = o1 - 7;  jv1 = 7 + q / 3;  si1 = q % 3; }
        else         { int q = o1 - 28; jv1 = 14 + q / 5; si1 = 3 + q % 5; }
    }

    float acc0 = 0.f, acc1 = 0.f;

#define MB(ii) { \
    int base = start + (ii); \
    int s = g_desrc[base]; \
    const float4* eap = (const float4*)(g_ead + (size_t)base * 8); \
    float4 a0 = __ldg(eap), a1v = __ldg(eap + 1); \
    float z = 0.f; \
    if (lane < 21) { \
        const float4* yp = (const float4*)(g_yv + (size_t)s * 168 + lane * 8); \
        float4 y0 = __ldg(yp), y1 = __ldg(yp + 1); \
        z = a0.x*y0.x + a0.y*y0.y + a0.z*y0.z + a0.w*y0.w \
          + a1v.x*y1.x + a1v.y*y1.y + a1v.z*y1.z; \
    } \
    float z0 = __shfl_sync(0xffffffffu, z, jv0); \
    float z1 = __shfl_sync(0xffffffffu, z, jv1); \
    const float* shp = g_shd + (size_t)base * 8; \
    float h0 = (si0 < 8) ? __ldg(shp + si0) : 1.f; \
    float h1 = (si1 < 8) ? __ldg(shp + si1) : 1.f; \
    acc0 = fmaf(z0, h0, acc0); \
    if (v1ok) acc1 = fmaf(z1, h1, acc1); \
}

    int i = 0;
    for (; i + 2 <= cnt; i += 2) { MB(i); MB(i + 1); }
    if (i < cnt) { MB(i); }
#undef MB

    g_m[(size_t)n * MDIM + o0] = acc0;
    if (v1ok) g_m[(size_t)n * MDIM + o1] = acc1;
    else if (lane == 31) g_m[(size_t)n * MDIM + 63] = 0.f;
}

// pass2: warp per dst node; lane strides edges, private m-row gather
__global__ void __launch_bounds__(256) k_pass2(
    const int* __restrict__ batch, float* __restrict__ out)
{
    int warp = (blockIdx.x * 256 + threadIdx.x) >> 5;
    int lane = threadIdx.x & 31;
    if (warp >= NN) return;
    int n = warp;
    int start = g_start_d[n];
    int cnt = g_start_d[n + 1] - start;

    float gsum = 0.f;
    for (int i = lane; i < cnt; i += 32) {
        int base = start + i;
        const float4* eap = (const float4*)(g_ead + (size_t)base * 8);
        float4 a0 = __ldg(eap), a1v = __ldg(eap + 1);
        const float4* shp = (const float4*)(g_shd + (size_t)base * 8);
        float4 h0 = __ldg(shp), h1 = __ldg(shp + 1);
        int s = g_desrc[base];

        float eav[NB] = { a0.x, a0.y, a0.z, a0.w, a1v.x, a1v.y, a1v.z };
        float mreg[64];
        const float4* mp = (const float4*)(g_m + (size_t)s * MDIM);
#pragma unroll
        for (int q = 0; q < 16; q++) ((float4*)mreg)[q] = __ldg(mp + q);

        float g = 0.f;
#pragma unroll
        for (int v = 0; v < NB; v++) {
            const float* m1v = mreg + 7 + v * 3;
            const float* m2v = mreg + 28 + v * 5;
            float t = mreg[v];
            t = fmaf(h0.x, m1v[0], t);
            t = fmaf(h0.y, m1v[1], t);
            t = fmaf(h0.z, m1v[2], t);
            t = fmaf(h0.w, m2v[0], t);
            t = fmaf(h1.x, m2v[1], t);
            t = fmaf(h1.y, m2v[2], t);
            t = fmaf(h1.z, m2v[3], t);
            t = fmaf(h1.w, m2v[4], t);
            g = fmaf(eav[v], t, g);
        }
        gsum += g;
    }

#pragma unroll
    for (int off = 16; off > 0; off >>= 1)
        gsum += __shfl_xor_sync(0xFFFFFFFFu, gsum, off);

    if (lane == 0) atomicAdd(&out[batch[n]], gsum);
}

extern "C" void kernel_launch(void* const* d_in, const int* in_sizes, int n_in,
                              void* d_out, int out_size) {
    const float* pos   = (const float*)d_in[0];
    const float* x     = (const float*)d_in[1];
    const float* ea    = (const float*)d_in[2];
    const int*   ei    = (const int*)d_in[3];
    const int*   batch = (const int*)d_in[4];
    const float* W1    = (const float*)d_in[5];
    const float* W2    = (const float*)d_in[6];
    const float* W3    = (const float*)d_in[7];
    const float* V1    = (const float*)d_in[8];
    const float* V2    = (const float*)d_in[9];
    const float* V3    = (const float*)d_in[10];
    float* out = (float*)d_out;

    k_count_wv<<<CNT_BLOCKS + WV_BLOCKS, 256>>>(ei, out, W1, W2, W3, V1, V2, V3);
    k_scan<<<1, 1024>>>();
    k_fill_yv<<<FILL_BLOCKS + YV_BLOCKS, 256>>>(ei, ea, pos, x);
    k_maccum<<<(NN * 32 + 255) / 256, 256>>>();
    k_pass2<<<(NN * 32 + 255) / 256, 256>>>(batch, out);
}

// round 15
// speedup vs baseline: 2.0783x; 1.0347x over previous
#include <cuda_runtime.h>

#define NN 20000
#define NE 320000
#define NG 256
#define NA 23
#define NB 7
#define M0 64
#define M1 24
#define M2 16
#define MDIM 64

#define CNT_BLOCKS ((NE + 255) / 256)            // 1250
#define WV_WARPS 3381
#define WV_BLOCKS ((WV_WARPS + 7) / 8)           // 423 (8 warps/block)
#define FILL_BLOCKS ((NE + 255) / 256)           // 1250
#define YV_BLOCKS 1000
#define YV_CHUNKS (NN / 8)                       // 2500

__device__ __align__(16) float g_wv[3381];                 // WV[(jv*7+v)*23 + u]
__device__ __align__(16) float g_yv[(size_t)NN * 168];     // yv[n][jv(21)*8 + v(7)]
__device__ __align__(16) float g_ead[(size_t)NE * 8];      // dst-sorted ea, padded
__device__ __align__(16) float g_shd[(size_t)NE * 8];      // dst-sorted sh1(3),sh2(5)
__device__ __align__(16) float g_m[(size_t)NN * MDIM];
__device__ int g_cnt_d[NN];                                // zeroed by k_scan after read
__device__ int g_cur_d[NN];
__device__ int g_start_d[NN + 1];
__device__ int g_desrc[NE];

#define A1  0.078811041f
#define C0  0.047245559f
#define C1  0.044543540f
#define C2  0.042257713f
#define S3  1.7320508075688772f
#define S5  2.23606797749979f
#define S15 3.872983346207417f

// merged: blocks [0, CNT_BLOCKS): count edges per dst + zero out;
//         blocks [CNT_BLOCKS, +WV_BLOCKS): WV warp-per-output.
__global__ void k_count_wv(const int* __restrict__ ei, float* __restrict__ out,
                           const float* __restrict__ W1, const float* __restrict__ W2,
                           const float* __restrict__ W3, const float* __restrict__ V1,
                           const float* __restrict__ V2, const float* __restrict__ V3) {
    if (blockIdx.x < CNT_BLOCKS) {
        int e = blockIdx.x * blockDim.x + threadIdx.x;
        if (e < NG) out[e] = 0.f;
        if (e < NE) atomicAdd(&g_cnt_d[ei[NE + e]], 1);
        return;
    }
    int wid = (blockIdx.x - CNT_BLOCKS) * 8 + (threadIdx.x >> 5);
    int lane = threadIdx.x & 31;
    if (wid >= WV_WARPS) return;
    int o = wid;
    int u = o % 23;
    int t = o / 23;
    int v = t % 7;
    int jv = t / 7;
    int j = jv / 7, vp = jv % 7;

    float r = 0.f;
    if (j == 0) {
        r = W1[(u*7+v)*M0 + lane] * V1[lane*7 + vp]
          + W1[(u*7+v)*M0 + lane + 32] * V1[(lane+32)*7 + vp];
    } else if (j == 1) {
        if (lane < M1) r = W2[(u*7+v)*M1 + lane] * V2[lane*7 + vp];
    } else {
        if (lane < M2) r = W3[(u*7+v)*M2 + lane] * V3[lane*7 + vp];
    }
#pragma unroll
    for (int off = 16; off > 0; off >>= 1)
        r += __shfl_xor_sync(0xffffffffu, r, off);
    if (lane == 0) {
        float sc = (j == 0) ? (A1 * C0) : (j == 1) ? (A1 * C1) : (A1 * C2);
        g_wv[o] = r * sc;
    }
}

// exclusive scan of cnt -> cur/start; self-cleans cnt back to 0 for next replay
__global__ void __launch_bounds__(1024) k_scan() {
    __shared__ int sums[1024];
    int t = threadIdx.x;
    int base = t * 20;
    int local[20]; int s = 0;
#pragma unroll
    for (int i = 0; i < 20; i++) {
        int idx = base + i;
        int c = 0;
        if (idx < NN) { c = g_cnt_d[idx]; g_cnt_d[idx] = 0; }
        local[i] = s; s += c;
    }
    sums[t] = s;
    __syncthreads();
    for (int d = 1; d < 1024; d <<= 1) {
        int v = (t >= d) ? sums[t - d] : 0;
        __syncthreads();
        if (t >= d) sums[t] += v;
        __syncthreads();
    }
    int excl = (t == 0) ? 0 : sums[t - 1];
#pragma unroll
    for (int i = 0; i < 20; i++) {
        int idx = base + i;
        if (idx < NN) { g_cur_d[idx] = excl + local[i]; g_start_d[idx] = excl + local[i]; }
    }
    if (t == 1023) g_start_d[NN] = sums[1023];
}

// merged: blocks [0, FILL_BLOCKS): dst-sort + stage ea/sh;
//         blocks [FILL_BLOCKS, +YV_BLOCKS): yv, 8 nodes per barrier.
__global__ void __launch_bounds__(256) k_fill_yv(
    const int* __restrict__ ei, const float* __restrict__ ea,
    const float* __restrict__ pos, const float* __restrict__ x)
{
    if (blockIdx.x < FILL_BLOCKS) {
        int e = blockIdx.x * 256 + threadIdx.x;
        if (e >= NE) return;
        int src = ei[e];
        int dst = ei[NE + e];
        int pd = atomicAdd(&g_cur_d[dst], 1);
        g_desrc[pd] = src;

        float a0 = __ldg(ea + e*7 + 0), a1 = __ldg(ea + e*7 + 1);
        float a2 = __ldg(ea + e*7 + 2), a3 = __ldg(ea + e*7 + 3);
        float a4 = __ldg(ea + e*7 + 4), a5 = __ldg(ea + e*7 + 5);
        float a6 = __ldg(ea + e*7 + 6);
        float4* eap = (float4*)(g_ead + (size_t)pd * 8);
        eap[0] = make_float4(a0, a1, a2, a3);
        eap[1] = make_float4(a4, a5, a6, 0.f);

        float px = __ldg(pos + src*3+0) - __ldg(pos + dst*3+0);
        float py = __ldg(pos + src*3+1) - __ldg(pos + dst*3+1);
        float pz = __ldg(pos + src*3+2) - __ldg(pos + dst*3+2);
        float r2 = px*px + py*py + pz*pz;
        float4* shp = (float4*)(g_shd + (size_t)pd * 8);
        shp[0] = make_float4(S3*px, S3*py, S3*pz, S15*px*py);
        shp[1] = make_float4(S15*py*pz, 0.5f*S5*(3.f*pz*pz - r2),
                             S15*px*pz, 0.5f*S15*(px*px - py*py));
        return;
    }

    // ---- yv branch: 8 nodes per chunk, one barrier per chunk ----
    __shared__ float xs[8 * NA];   // 184 floats, contiguous rows of x
    int t = threadIdx.x;
    bool act = t < 147;
    float wreg[NA];
    if (act) {
#pragma unroll
        for (int u = 0; u < NA; u++) wreg[u] = g_wv[t * 23 + u];
    }
    int jv = t / 7, v = t % 7;
    int off = jv * 8 + v;

    for (int c = blockIdx.x - FILL_BLOCKS; c < YV_CHUNKS; c += YV_BLOCKS) {
        int n0 = c * 8;
        __syncthreads();
        if (t < 8 * NA) xs[t] = x[n0 * NA + t];   // coalesced
        __syncthreads();
        if (!act) continue;
        float acc[8];
#pragma unroll
        for (int k = 0; k < 8; k++) acc[k] = 0.f;
#pragma unroll
        for (int u = 0; u < NA; u++) {
            float w = wreg[u];
#pragma unroll
            for (int k = 0; k < 8; k++)
                acc[k] = fmaf(xs[k * NA + u], w, acc[k]);
        }
#pragma unroll
        for (int k = 0; k < 8; k++)
            g_yv[(size_t)(n0 + k) * 168 + off] = acc[k];
    }
}

// maccum: TWO warps per dst node (halved serial chain), smem combine.
// Block = 8 warps = 4 nodes. Lanes 0-20 compute z[jv] once (coalesced yv row);
// shuffles distribute z to the 63 output lanes.
__global__ void __launch_bounds__(256) k_maccum() {
    __shared__ float part[8][64];

    int wIdx = threadIdx.x >> 5;          // 0..7
    int lane = threadIdx.x & 31;
    int n = blockIdx.x * 4 + (wIdx >> 1); // NN % 4 == 0, no guard
    int h = wIdx & 1;

    int start = g_start_d[n];
    int cnt = g_start_d[n + 1] - start;
    int half = (cnt + 1) >> 1;
    int lo = h ? half : 0;
    int hi = h ? cnt : half;

    int o0 = lane, o1 = lane + 32;
    int jv0, si0, jv1 = 0, si1 = 8;
    if (o0 < 7)       { jv0 = o0; si0 = 8; }
    else if (o0 < 28) { int q = o0 - 7;  jv0 = 7 + q / 3;  si0 = q % 3; }
    else              { int q = o0 - 28; jv0 = 14 + q / 5; si0 = 3 + q % 5; }
    bool v1ok = o1 < 63;
    if (v1ok) {
        if (o1 < 28) { int q = o1 - 7;  jv1 = 7 + q / 3;  si1 = q % 3; }
        else         { int q = o1 - 28; jv1 = 14 + q / 5; si1 = 3 + q % 5; }
    }

    float acc0 = 0.f, acc1 = 0.f;

#define MB(ii) { \
    int base = start + (ii); \
    int s = g_desrc[base]; \
    const float4* eap = (const float4*)(g_ead + (size_t)base * 8); \
    float4 a0 = __ldg(eap), a1v = __ldg(eap + 1); \
    float z = 0.f; \
    if (lane < 21) { \
        const float4* yp = (const float4*)(g_yv + (size_t)s * 168 + lane * 8); \
        float4 y0 = __ldg(yp), y1 = __ldg(yp + 1); \
        z = a0.x*y0.x + a0.y*y0.y + a0.z*y0.z + a0.w*y0.w \
          + a1v.x*y1.x + a1v.y*y1.y + a1v.z*y1.z; \
    } \
    float z0 = __shfl_sync(0xffffffffu, z, jv0); \
    float z1 = __shfl_sync(0xffffffffu, z, jv1); \
    const float* shp = g_shd + (size_t)base * 8; \
    float hh0 = (si0 < 8) ? __ldg(shp + si0) : 1.f; \
    float hh1 = (si1 < 8) ? __ldg(shp + si1) : 1.f; \
    acc0 = fmaf(z0, hh0, acc0); \
    if (v1ok) acc1 = fmaf(z1, hh1, acc1); \
}

    int i = lo;
    for (; i + 2 <= hi; i += 2) { MB(i); MB(i + 1); }
    if (i < hi) { MB(i); }
#undef MB

    part[wIdx][o0] = acc0;
    part[wIdx][o1] = acc1;                 // lane 31: acc1 == 0 -> m[63] = 0
    __syncthreads();

    int k = threadIdx.x >> 6;              // 0..3 node-local
    int o = threadIdx.x & 63;
    int n2 = blockIdx.x * 4 + k;
    g_m[(size_t)n2 * MDIM + o] = part[2 * k][o] + part[2 * k + 1][o];
}

// pass2: warp per dst node; lane strides edges, private m-row gather
__global__ void __launch_bounds__(256) k_pass2(
    const int* __restrict__ batch, float* __restrict__ out)
{
    int warp = (blockIdx.x * 256 + threadIdx.x) >> 5;
    int lane = threadIdx.x & 31;
    if (warp >= NN) return;
    int n = warp;
    int start = g_start_d[n];
    int cnt = g_start_d[n + 1] - start;

    float gsum = 0.f;
    for (int i = lane; i < cnt; i += 32) {
        int base = start + i;
        const float4* eap = (const float4*)(g_ead + (size_t)base * 8);
        float4 a0 = __ldg(eap), a1v = __ldg(eap + 1);
        const float4* shp = (const float4*)(g_shd + (size_t)base * 8);
        float4 h0 = __ldg(shp), h1 = __ldg(shp + 1);
        int s = g_desrc[base];

        float eav[NB] = { a0.x, a0.y, a0.z, a0.w, a1v.x, a1v.y, a1v.z };
        float mreg[64];
        const float4* mp = (const float4*)(g_m + (size_t)s * MDIM);
#pragma unroll
        for (int q = 0; q < 16; q++) ((float4*)mreg)[q] = __ldg(mp + q);

        float g = 0.f;
#pragma unroll
        for (int v = 0; v < NB; v++) {
            const float* m1v = mreg + 7 + v * 3;
            const float* m2v = mreg + 28 + v * 5;
            float t = mreg[v];
            t = fmaf(h0.x, m1v[0], t);
            t = fmaf(h0.y, m1v[1], t);
            t = fmaf(h0.z, m1v[2], t);
            t = fmaf(h0.w, m2v[0], t);
            t = fmaf(h1.x, m2v[1], t);
            t = fmaf(h1.y, m2v[2], t);
            t = fmaf(h1.z, m2v[3], t);
            t = fmaf(h1.w, m2v[4], t);
            g = fmaf(eav[v], t, g);
        }
        gsum += g;
    }

#pragma unroll
    for (int off = 16; off > 0; off >>= 1)
        gsum += __shfl_xor_sync(0xFFFFFFFFu, gsum, off);

    if (lane == 0) atomicAdd(&out[batch[n]], gsum);
}

extern "C" void kernel_launch(void* const* d_in, const int* in_sizes, int n_in,
                              void* d_out, int out_size) {
    const float* pos   = (const float*)d_in[0];
    const float* x     = (const float*)d_in[1];
    const float* ea    = (const float*)d_in[2];
    const int*   ei    = (const int*)d_in[3];
    const int*   batch = (const int*)d_in[4];
    const float* W1    = (const float*)d_in[5];
    const float* W2    = (const float*)d_in[6];
    const float* W3    = (const float*)d_in[7];
    const float* V1    = (const float*)d_in[8];
    const float* V2    = (const float*)d_in[9];
    const float* V3    = (const float*)d_in[10];
    float* out = (float*)d_out;

    k_count_wv<<<CNT_BLOCKS + WV_BLOCKS, 256>>>(ei, out, W1, W2, W3, V1, V2, V3);
    k_scan<<<1, 1024>>>();
    k_fill_yv<<<FILL_BLOCKS + YV_BLOCKS, 256>>>(ei, ea, pos, x);
    k_maccum<<<NN / 4, 256>>>();
    k_pass2<<<(NN * 32 + 255) / 256, 256>>>(batch, out);
}